// round 12
// baseline (speedup 1.0000x reference)
#include <cuda_runtime.h>

// ---------------------------------------------------------------------------
// Inverse DTCWT, 2 levels.
//   kA: level-1 fused (vertical qshift 4 k-groups -> smem -> horizontal) -> g_Z
//   kB: level-0 biort fused tiled, 16 rows/block -> out
// ---------------------------------------------------------------------------

#define SCQ 0.70710678118654752f

__constant__ float cF0[4][7] = {
  { 0.00325314f,  0.03466035f, -0.11720389f,  0.75614564f,  0.01186609f,  0.02382538f, -0.00543948f},
  {-0.00455690f,  0.01702522f, -0.10671180f,  0.56881042f,  0.27529538f, -0.03887280f, -0.00388321f},
  {-0.00388321f, -0.03887280f,  0.27529538f,  0.56881042f, -0.10671180f,  0.01702522f, -0.00455690f},
  {-0.00543948f,  0.02382538f,  0.01186609f,  0.75614564f, -0.11720389f,  0.03466035f,  0.00325314f}
};
__constant__ float cF1[4][7] = {
  {-0.00455690f,  0.01702522f, -0.10671180f,  0.56881042f,  0.27529538f, -0.03887280f, -0.00388321f},
  {-0.00325314f, -0.03466035f,  0.11720389f, -0.75614564f, -0.01186609f, -0.02382538f,  0.00543948f},
  { 0.00543948f, -0.02382538f, -0.01186609f, -0.75614564f,  0.11720389f, -0.03466035f, -0.00325314f},
  {-0.00388321f, -0.03887280f,  0.27529538f,  0.56881042f, -0.10671180f,  0.01702522f, -0.00455690f}
};
__constant__ float cG0[7] = {-0.0107142857142857f, -0.0535714285714286f, 0.2607142857142857f,
                              0.6071428571428571f,  0.2607142857142857f, -0.0535714285714286f,
                             -0.0107142857142857f};
__constant__ float cG1[5] = {-0.05f, -0.25f, 0.6f, -0.25f, -0.05f};

__device__ float g_Z[8 * 512 * 512 * 3];

__device__ __forceinline__ int refl(int p, int L) {
  return p < 0 ? (-1 - p) : (p >= L ? (2 * L - 1 - p) : p);
}
__device__ __forceinline__ float comb(float x, float y, int rp, int wp) {
  return rp == 0 ? (x + y) : (wp == 0 ? (x - y) : (y - x));
}

// ---------------- kA: level-1 fused, tile = 16 Z-rows x 128 Z-cols ----------
// grid (4, 32, 8), block 256.
// Phase 1: 228 lanes = 76 y-cols x 3 ch, 4 k-groups (16 rows) each, 4 passes.
// Phase 2: 512 items (16 rows x 32 k-groups), 2 per thread, -> g_Z.
__global__ __launch_bounds__(256) void kA_lvl1(const float* __restrict__ low,
                                               const float* __restrict__ hi1) {
  __shared__ float sY1[16][228];
  __shared__ float sY2[16][228];
  int kw0 = blockIdx.x * 32;
  int by  = blockIdx.y;              // rows 16*by .. 16*by+15 ; k = 4*by+dk
  int b   = blockIdx.z;
  int t   = threadIdx.x;

  if (t < 228) {
    int z = t / 3, c = t - 3 * z;
    int yc = 2 * kw0 - 6 + z;
    int yr = refl(yc, 256);
    int jj = yr >> 1, wp = yr & 1;
    const bool interior = (by >= 1 && by <= 30);
    const int base = 8 * by - 6;     // window rows base..base+19

    const float* lowb = low + ((b * 256) * 256 + yr) * 3 + c;
    const float* hb   = hi1 + ((b * 128) * 128 + jj) * 36 + c;

    float a[16], hl[16];
    // ---- pass 1: low stream -> a ----
    {
      float xl[20];
#pragma unroll
      for (int v = 0; v < 20; v++) {
        int p = base + v;
        if (!interior) p = refl(p, 256);
        xl[v] = lowb[p * 768];
      }
#pragma unroll
      for (int dk = 0; dk < 4; dk++)
#pragma unroll
        for (int s = 0; s < 4; s++) {
          int v0 = 2 * dk + 12 + (s & 1);
          float acc = 0.f;
#pragma unroll
          for (int j = 0; j < 7; j++) acc += cF0[s][j] * xl[v0 - 2 * j];
          a[4 * dk + s] = acc;
        }
    }
    // ---- pass 2: hl stream -> hl ----
    {
      float xB[20];
#pragma unroll
      for (int v = 0; v < 20; v++) {
        int p = base + v;
        if (!interior) p = refl(p, 256);
        int i = p >> 1, rp = p & 1;
        const float* q = hb + i * 4608 + ((rp ^ wp) ? 18 : 0);
        xB[v] = comb(q[6], q[9], rp, wp);
      }
#pragma unroll
      for (int dk = 0; dk < 4; dk++)
#pragma unroll
        for (int s = 0; s < 4; s++) {
          int v0 = 2 * dk + 12 + (s & 1);
          float acc = 0.f;
#pragma unroll
          for (int j = 0; j < 7; j++) acc += cF0[s][j] * xB[v0 - 2 * j];
          hl[4 * dk + s] = acc;
        }
    }
    // ---- pass 3: lh stream -> sY1 ----
    {
      float xC[20];
#pragma unroll
      for (int v = 0; v < 20; v++) {
        int p = base + v;
        if (!interior) p = refl(p, 256);
        int i = p >> 1, rp = p & 1;
        const float* q = hb + i * 4608 + ((rp ^ wp) ? 18 : 0);
        xC[v] = comb(q[0], q[15], rp, wp);
      }
#pragma unroll
      for (int dk = 0; dk < 4; dk++)
#pragma unroll
        for (int s = 0; s < 4; s++) {
          int v1 = 2 * dk + 13 - (s & 1);
          float acc = 0.f;
#pragma unroll
          for (int j = 0; j < 7; j++) acc += cF1[s][j] * xC[v1 - 2 * j];
          sY1[4 * dk + s][t] = a[4 * dk + s] + SCQ * acc;
        }
    }
    // ---- pass 4: hh stream -> sY2 ----
    {
      float xD[20];
#pragma unroll
      for (int v = 0; v < 20; v++) {
        int p = base + v;
        if (!interior) p = refl(p, 256);
        int i = p >> 1, rp = p & 1;
        const float* q = hb + i * 4608 + ((rp ^ wp) ? 18 : 0);
        xD[v] = comb(q[3], q[12], rp, wp);
      }
#pragma unroll
      for (int dk = 0; dk < 4; dk++)
#pragma unroll
        for (int s = 0; s < 4; s++) {
          int v1 = 2 * dk + 13 - (s & 1);
          float acc = 0.f;
#pragma unroll
          for (int j = 0; j < 7; j++) acc += cF1[s][j] * xD[v1 - 2 * j];
          sY2[4 * dk + s][t] = SCQ * (hl[4 * dk + s] + acc);
        }
    }
  }
  __syncthreads();

  // ---- phase 2: horizontal qshift from smem -> g_Z (2 items/thread) ----
#pragma unroll
  for (int it = 0; it < 2; it++) {
    int id = t + 256 * it;
    int row = id >> 5, cp = id & 31;
    float O[12];
#pragma unroll
    for (int i = 0; i < 12; i++) O[i] = 0.f;
#pragma unroll
    for (int s = 0; s < 4; s++) {
      int v0 = 2 * cp + 12 + (s & 1), v1 = 2 * cp + 13 - (s & 1);
#pragma unroll
      for (int j = 0; j < 7; j++) {
        float f0 = cF0[s][j], f1 = cF1[s][j];
#pragma unroll
        for (int c = 0; c < 3; c++) {
          O[s * 3 + c] += f0 * sY1[row][(v0 - 2 * j) * 3 + c]
                        + f1 * sY2[row][(v1 - 2 * j) * 3 + c];
        }
      }
    }
    int ob = ((b * 512 + 16 * by + row) * 512 + 4 * (kw0 + cp)) * 3;
    float4* po = (float4*)(g_Z + ob);
#pragma unroll
    for (int m = 0; m < 3; m++)
      po[m] = make_float4(O[4 * m], O[4 * m + 1], O[4 * m + 2], O[4 * m + 3]);
  }
}

// ---------------- kB: level-0 fused, tiled 16 rows x 64 cols ----------------
// grid (8, 32, 8); block 256. 4-pass phase 1, 210 active lanes.
__global__ __launch_bounds__(256) void kB_lvl0(const float* __restrict__ hi0,
                                               float* __restrict__ out) {
  __shared__ float sY1[16][210];
  __shared__ float sY2[16][210];
  int wt = blockIdx.x * 64;
  int rt = blockIdx.y * 16;
  int b  = blockIdx.z;
  int t  = threadIdx.x;

  if (t < 210) {
    int ucol = t / 3, c = t - 3 * ucol;
    int w  = wt - 3 + ucol;
    int wr = refl(w, 512);
    int jj = wr >> 1, wp = wr & 1;
    const float* zb = g_Z + ((b * 512) * 512 + wr) * 3 + c;
    const float* hb = hi0 + ((b * 256) * 256 + jj) * 36 + c;
    const bool vint = (rt >= 4 && rt <= 493);

    float a1[16], a2[16];
    // ---- pass Z: xz[22] -> a1 ----
    {
      float xz[22];
#pragma unroll
      for (int v = 0; v < 22; v++) {
        int p = rt - 3 + v;
        if (!vint) p = refl(p, 512);
        xz[v] = zb[p * 1536];
      }
#pragma unroll
      for (int s = 0; s < 16; s++) {
        float acc = 0.f;
#pragma unroll
        for (int j = 0; j < 7; j++) acc += cG0[j] * xz[s + 6 - j];
        a1[s] = acc;
      }
    }
    // ---- pass A: xhl[22] -> a2 ----
    {
      float xhl[22];
#pragma unroll
      for (int v = 0; v < 22; v++) {
        int p = rt - 3 + v;
        if (!vint) p = refl(p, 512);
        int i = p >> 1, rp = p & 1;
        const float* qq = hb + i * 9216 + ((rp ^ wp) ? 18 : 0);
        xhl[v] = comb(qq[6], qq[9], rp, wp);
      }
#pragma unroll
      for (int s = 0; s < 16; s++) {
        float acc = 0.f;
#pragma unroll
        for (int j = 0; j < 7; j++) acc += cG0[j] * xhl[s + 6 - j];
        a2[s] = acc;
      }
    }
    // ---- pass B1: xlh[20] -> sY1 ----
    {
      float xlh[20];
#pragma unroll
      for (int v = 0; v < 20; v++) {
        int p = rt - 2 + v;
        if (!vint) p = refl(p, 512);
        int i = p >> 1, rp = p & 1;
        const float* qq = hb + i * 9216 + ((rp ^ wp) ? 18 : 0);
        xlh[v] = comb(qq[0], qq[15], rp, wp);
      }
#pragma unroll
      for (int s = 0; s < 16; s++) {
        float acc = 0.f;
#pragma unroll
        for (int j = 0; j < 5; j++) acc += cG1[j] * xlh[s + 4 - j];
        sY1[s][t] = a1[s] + SCQ * acc;
      }
    }
    // ---- pass B2: xhh[20] -> sY2 ----
    {
      float xhh[20];
#pragma unroll
      for (int v = 0; v < 20; v++) {
        int p = rt - 2 + v;
        if (!vint) p = refl(p, 512);
        int i = p >> 1, rp = p & 1;
        const float* qq = hb + i * 9216 + ((rp ^ wp) ? 18 : 0);
        xhh[v] = comb(qq[3], qq[12], rp, wp);
      }
#pragma unroll
      for (int s = 0; s < 16; s++) {
        float acc = 0.f;
#pragma unroll
        for (int j = 0; j < 5; j++) acc += cG1[j] * xhh[s + 4 - j];
        sY2[s][t] = SCQ * (a2[s] + acc);
      }
    }
  }
  __syncthreads();

  // ---- phase 2: 16 rows x 16 col-groups, 4 cols x 3 ch per thread ----
  int row = t >> 4, cp = t & 15;
  int cc0 = 4 * cp;
  float o[12];
#pragma unroll
  for (int d = 0; d < 4; d++) {
    int cc = cc0 + d;
#pragma unroll
    for (int ch = 0; ch < 3; ch++) {
      float acc = 0.f;
#pragma unroll
      for (int j = 0; j < 7; j++) acc += cG0[j] * sY1[row][(cc + 6 - j) * 3 + ch];
#pragma unroll
      for (int j = 0; j < 5; j++) acc += cG1[j] * sY2[row][(cc + 5 - j) * 3 + ch];
      o[d * 3 + ch] = acc;
    }
  }
  int ob = ((b * 512 + rt + row) * 512 + wt + cc0) * 3;
  float4* po = (float4*)(out + ob);
#pragma unroll
  for (int m = 0; m < 3; m++)
    po[m] = make_float4(o[4 * m], o[4 * m + 1], o[4 * m + 2], o[4 * m + 3]);
}

extern "C" void kernel_launch(void* const* d_in, const int* in_sizes, int n_in,
                              void* d_out, int out_size) {
  const float *low = nullptr, *high0 = nullptr, *high1 = nullptr;
  for (int i = 0; i < n_in; i++) {
    if (in_sizes[i] == 8 * 256 * 256 * 3)       low   = (const float*)d_in[i];
    else if (in_sizes[i] == 8 * 256 * 256 * 36) high0 = (const float*)d_in[i];
    else if (in_sizes[i] == 8 * 128 * 128 * 36) high1 = (const float*)d_in[i];
  }
  float* out = (float*)d_out;

  kA_lvl1<<<dim3(4, 32, 8), 256>>>(low, high1);
  kB_lvl0<<<dim3(8, 32, 8), 256>>>(high0, out);
}

// round 13
// speedup vs baseline: 1.1223x; 1.1223x over previous
#include <cuda_runtime.h>

// ---------------------------------------------------------------------------
// Inverse DTCWT, 2 levels. 16-row tiles with shared-memory partial accumulation
// (keeps per-pass register footprint to one window array).
//   kA: level-1 fused qshift -> g_Z
//   kB: level-0 fused biort  -> out
// ---------------------------------------------------------------------------

#define SCQ 0.70710678118654752f

__constant__ float cF0[4][7] = {
  { 0.00325314f,  0.03466035f, -0.11720389f,  0.75614564f,  0.01186609f,  0.02382538f, -0.00543948f},
  {-0.00455690f,  0.01702522f, -0.10671180f,  0.56881042f,  0.27529538f, -0.03887280f, -0.00388321f},
  {-0.00388321f, -0.03887280f,  0.27529538f,  0.56881042f, -0.10671180f,  0.01702522f, -0.00455690f},
  {-0.00543948f,  0.02382538f,  0.01186609f,  0.75614564f, -0.11720389f,  0.03466035f,  0.00325314f}
};
__constant__ float cF1[4][7] = {
  {-0.00455690f,  0.01702522f, -0.10671180f,  0.56881042f,  0.27529538f, -0.03887280f, -0.00388321f},
  {-0.00325314f, -0.03466035f,  0.11720389f, -0.75614564f, -0.01186609f, -0.02382538f,  0.00543948f},
  { 0.00543948f, -0.02382538f, -0.01186609f, -0.75614564f,  0.11720389f, -0.03466035f, -0.00325314f},
  {-0.00388321f, -0.03887280f,  0.27529538f,  0.56881042f, -0.10671180f,  0.01702522f, -0.00455690f}
};
__constant__ float cG0[7] = {-0.0107142857142857f, -0.0535714285714286f, 0.2607142857142857f,
                              0.6071428571428571f,  0.2607142857142857f, -0.0535714285714286f,
                             -0.0107142857142857f};
__constant__ float cG1[5] = {-0.05f, -0.25f, 0.6f, -0.25f, -0.05f};

__device__ float g_Z[8 * 512 * 512 * 3];

__device__ __forceinline__ int refl(int p, int L) {
  return p < 0 ? (-1 - p) : (p >= L ? (2 * L - 1 - p) : p);
}
__device__ __forceinline__ float comb(float x, float y, int rp, int wp) {
  return rp == 0 ? (x + y) : (wp == 0 ? (x - y) : (y - x));
}

// ---------------- kA: level-1 fused, tile = 16 Z-rows x 128 Z-cols ----------
// grid (4, 32, 8), block 256. smem-accumulated 4-pass vertical, then horizontal.
__global__ __launch_bounds__(256) void kA_lvl1(const float* __restrict__ low,
                                               const float* __restrict__ hi1) {
  __shared__ float sY1[16][228];
  __shared__ float sY2[16][228];
  int kw0 = blockIdx.x * 32;
  int by  = blockIdx.y;              // Z rows 16*by .. 16*by+15
  int b   = blockIdx.z;
  int t   = threadIdx.x;

  if (t < 228) {
    int z = t / 3, c = t - 3 * z;
    int yc = 2 * kw0 - 6 + z;
    int yr = refl(yc, 256);
    int jj = yr >> 1, wp = yr & 1;
    const bool interior = (by >= 1 && by <= 30);
    const int base = 8 * by - 6;     // window rows base..base+19

    const float* lowb = low + ((b * 256) * 256 + yr) * 3 + c;
    const float* hb   = hi1 + ((b * 128) * 128 + jj) * 36 + c;

    // ---- pass 1: low stream -> sY1 partial ----
    {
      float x[20];
#pragma unroll
      for (int v = 0; v < 20; v++) {
        int p = base + v;
        if (!interior) p = refl(p, 256);
        x[v] = lowb[p * 768];
      }
#pragma unroll
      for (int dk = 0; dk < 4; dk++)
#pragma unroll
        for (int s = 0; s < 4; s++) {
          int v0 = 2 * dk + 12 + (s & 1);
          float acc = 0.f;
#pragma unroll
          for (int j = 0; j < 7; j++) acc += cF0[s][j] * x[v0 - 2 * j];
          sY1[4 * dk + s][t] = acc;
        }
    }
    // ---- pass 2: hl stream -> sY2 partial ----
    {
      float x[20];
#pragma unroll
      for (int v = 0; v < 20; v++) {
        int p = base + v;
        if (!interior) p = refl(p, 256);
        int i = p >> 1, rp = p & 1;
        const float* q = hb + i * 4608 + ((rp ^ wp) ? 18 : 0);
        x[v] = comb(q[6], q[9], rp, wp);
      }
#pragma unroll
      for (int dk = 0; dk < 4; dk++)
#pragma unroll
        for (int s = 0; s < 4; s++) {
          int v0 = 2 * dk + 12 + (s & 1);
          float acc = 0.f;
#pragma unroll
          for (int j = 0; j < 7; j++) acc += cF0[s][j] * x[v0 - 2 * j];
          sY2[4 * dk + s][t] = acc;
        }
    }
    // ---- pass 3: lh stream -> sY1 final ----
    {
      float x[20];
#pragma unroll
      for (int v = 0; v < 20; v++) {
        int p = base + v;
        if (!interior) p = refl(p, 256);
        int i = p >> 1, rp = p & 1;
        const float* q = hb + i * 4608 + ((rp ^ wp) ? 18 : 0);
        x[v] = comb(q[0], q[15], rp, wp);
      }
#pragma unroll
      for (int dk = 0; dk < 4; dk++)
#pragma unroll
        for (int s = 0; s < 4; s++) {
          int v1 = 2 * dk + 13 - (s & 1);
          float acc = 0.f;
#pragma unroll
          for (int j = 0; j < 7; j++) acc += cF1[s][j] * x[v1 - 2 * j];
          sY1[4 * dk + s][t] += SCQ * acc;
        }
    }
    // ---- pass 4: hh stream -> sY2 final ----
    {
      float x[20];
#pragma unroll
      for (int v = 0; v < 20; v++) {
        int p = base + v;
        if (!interior) p = refl(p, 256);
        int i = p >> 1, rp = p & 1;
        const float* q = hb + i * 4608 + ((rp ^ wp) ? 18 : 0);
        x[v] = comb(q[3], q[12], rp, wp);
      }
#pragma unroll
      for (int dk = 0; dk < 4; dk++)
#pragma unroll
        for (int s = 0; s < 4; s++) {
          int v1 = 2 * dk + 13 - (s & 1);
          float acc = 0.f;
#pragma unroll
          for (int j = 0; j < 7; j++) acc += cF1[s][j] * x[v1 - 2 * j];
          sY2[4 * dk + s][t] = SCQ * (sY2[4 * dk + s][t] + acc);
        }
    }
  }
  __syncthreads();

  // ---- phase 2: horizontal qshift from smem -> g_Z (2 items/thread) ----
#pragma unroll
  for (int it = 0; it < 2; it++) {
    int id = t + 256 * it;
    int row = id >> 5, cp = id & 31;
    float O[12];
#pragma unroll
    for (int i = 0; i < 12; i++) O[i] = 0.f;
#pragma unroll
    for (int s = 0; s < 4; s++) {
      int v0 = 2 * cp + 12 + (s & 1), v1 = 2 * cp + 13 - (s & 1);
#pragma unroll
      for (int j = 0; j < 7; j++) {
        float f0 = cF0[s][j], f1 = cF1[s][j];
#pragma unroll
        for (int c = 0; c < 3; c++) {
          O[s * 3 + c] += f0 * sY1[row][(v0 - 2 * j) * 3 + c]
                        + f1 * sY2[row][(v1 - 2 * j) * 3 + c];
        }
      }
    }
    int ob = ((b * 512 + 16 * by + row) * 512 + 4 * (kw0 + cp)) * 3;
    float4* po = (float4*)(g_Z + ob);
#pragma unroll
    for (int m = 0; m < 3; m++)
      po[m] = make_float4(O[4 * m], O[4 * m + 1], O[4 * m + 2], O[4 * m + 3]);
  }
}

// ---------------- kB: level-0 fused, tiled 16 rows x 64 cols ----------------
// grid (8, 32, 8); block 256. smem-accumulated 4-pass vertical, then horizontal.
__global__ __launch_bounds__(256) void kB_lvl0(const float* __restrict__ hi0,
                                               float* __restrict__ out) {
  __shared__ float sY1[16][210];
  __shared__ float sY2[16][210];
  int wt = blockIdx.x * 64;
  int rt = blockIdx.y * 16;
  int b  = blockIdx.z;
  int t  = threadIdx.x;

  if (t < 210) {
    int ucol = t / 3, c = t - 3 * ucol;
    int w  = wt - 3 + ucol;
    int wr = refl(w, 512);
    int jj = wr >> 1, wp = wr & 1;
    const float* zb = g_Z + ((b * 512) * 512 + wr) * 3 + c;
    const float* hb = hi0 + ((b * 256) * 256 + jj) * 36 + c;
    const bool vint = (rt >= 4 && rt <= 493);

    // ---- pass Z: xz[22] -> sY1 partial ----
    {
      float x[22];
#pragma unroll
      for (int v = 0; v < 22; v++) {
        int p = rt - 3 + v;
        if (!vint) p = refl(p, 512);
        x[v] = zb[p * 1536];
      }
#pragma unroll
      for (int s = 0; s < 16; s++) {
        float acc = 0.f;
#pragma unroll
        for (int j = 0; j < 7; j++) acc += cG0[j] * x[s + 6 - j];
        sY1[s][t] = acc;
      }
    }
    // ---- pass hl: xhl[22] -> sY2 partial ----
    {
      float x[22];
#pragma unroll
      for (int v = 0; v < 22; v++) {
        int p = rt - 3 + v;
        if (!vint) p = refl(p, 512);
        int i = p >> 1, rp = p & 1;
        const float* qq = hb + i * 9216 + ((rp ^ wp) ? 18 : 0);
        x[v] = comb(qq[6], qq[9], rp, wp);
      }
#pragma unroll
      for (int s = 0; s < 16; s++) {
        float acc = 0.f;
#pragma unroll
        for (int j = 0; j < 7; j++) acc += cG0[j] * x[s + 6 - j];
        sY2[s][t] = acc;
      }
    }
    // ---- pass lh: xlh[20] -> sY1 final ----
    {
      float x[20];
#pragma unroll
      for (int v = 0; v < 20; v++) {
        int p = rt - 2 + v;
        if (!vint) p = refl(p, 512);
        int i = p >> 1, rp = p & 1;
        const float* qq = hb + i * 9216 + ((rp ^ wp) ? 18 : 0);
        x[v] = comb(qq[0], qq[15], rp, wp);
      }
#pragma unroll
      for (int s = 0; s < 16; s++) {
        float acc = 0.f;
#pragma unroll
        for (int j = 0; j < 5; j++) acc += cG1[j] * x[s + 4 - j];
        sY1[s][t] += SCQ * acc;
      }
    }
    // ---- pass hh: xhh[20] -> sY2 final ----
    {
      float x[20];
#pragma unroll
      for (int v = 0; v < 20; v++) {
        int p = rt - 2 + v;
        if (!vint) p = refl(p, 512);
        int i = p >> 1, rp = p & 1;
        const float* qq = hb + i * 9216 + ((rp ^ wp) ? 18 : 0);
        x[v] = comb(qq[3], qq[12], rp, wp);
      }
#pragma unroll
      for (int s = 0; s < 16; s++) {
        float acc = 0.f;
#pragma unroll
        for (int j = 0; j < 5; j++) acc += cG1[j] * x[s + 4 - j];
        sY2[s][t] = SCQ * (sY2[s][t] + acc);
      }
    }
  }
  __syncthreads();

  // ---- phase 2: 16 rows x 16 col-groups, 4 cols x 3 ch per thread ----
  int row = t >> 4, cp = t & 15;
  int cc0 = 4 * cp;
  float o[12];
#pragma unroll
  for (int d = 0; d < 4; d++) {
    int cc = cc0 + d;
#pragma unroll
    for (int ch = 0; ch < 3; ch++) {
      float acc = 0.f;
#pragma unroll
      for (int j = 0; j < 7; j++) acc += cG0[j] * sY1[row][(cc + 6 - j) * 3 + ch];
#pragma unroll
      for (int j = 0; j < 5; j++) acc += cG1[j] * sY2[row][(cc + 5 - j) * 3 + ch];
      o[d * 3 + ch] = acc;
    }
  }
  int ob = ((b * 512 + rt + row) * 512 + wt + cc0) * 3;
  float4* po = (float4*)(out + ob);
#pragma unroll
  for (int m = 0; m < 3; m++)
    po[m] = make_float4(o[4 * m], o[4 * m + 1], o[4 * m + 2], o[4 * m + 3]);
}

extern "C" void kernel_launch(void* const* d_in, const int* in_sizes, int n_in,
                              void* d_out, int out_size) {
  const float *low = nullptr, *high0 = nullptr, *high1 = nullptr;
  for (int i = 0; i < n_in; i++) {
    if (in_sizes[i] == 8 * 256 * 256 * 3)       low   = (const float*)d_in[i];
    else if (in_sizes[i] == 8 * 256 * 256 * 36) high0 = (const float*)d_in[i];
    else if (in_sizes[i] == 8 * 128 * 128 * 36) high1 = (const float*)d_in[i];
  }
  float* out = (float*)d_out;

  kA_lvl1<<<dim3(4, 32, 8), 256>>>(low, high1);
  kB_lvl0<<<dim3(8, 32, 8), 256>>>(high0, out);
}

// round 14
// speedup vs baseline: 1.2253x; 1.0918x over previous
#include <cuda_runtime.h>

// ---------------------------------------------------------------------------
// Inverse DTCWT, 2 levels.
//   kA: level-1 fused qshift, 8-row tile (R11 proven) -> g_Z
//   kB: level-0 fused biort, 8-row tile, hi0 row-staged in smem -> out
// ---------------------------------------------------------------------------

#define SCQ 0.70710678118654752f

__constant__ float cF0[4][7] = {
  { 0.00325314f,  0.03466035f, -0.11720389f,  0.75614564f,  0.01186609f,  0.02382538f, -0.00543948f},
  {-0.00455690f,  0.01702522f, -0.10671180f,  0.56881042f,  0.27529538f, -0.03887280f, -0.00388321f},
  {-0.00388321f, -0.03887280f,  0.27529538f,  0.56881042f, -0.10671180f,  0.01702522f, -0.00455690f},
  {-0.00543948f,  0.02382538f,  0.01186609f,  0.75614564f, -0.11720389f,  0.03466035f,  0.00325314f}
};
__constant__ float cF1[4][7] = {
  {-0.00455690f,  0.01702522f, -0.10671180f,  0.56881042f,  0.27529538f, -0.03887280f, -0.00388321f},
  {-0.00325314f, -0.03466035f,  0.11720389f, -0.75614564f, -0.01186609f, -0.02382538f,  0.00543948f},
  { 0.00543948f, -0.02382538f, -0.01186609f, -0.75614564f,  0.11720389f, -0.03466035f, -0.00325314f},
  {-0.00388321f, -0.03887280f,  0.27529538f,  0.56881042f, -0.10671180f,  0.01702522f, -0.00455690f}
};
__constant__ float cG0[7] = {-0.0107142857142857f, -0.0535714285714286f, 0.2607142857142857f,
                              0.6071428571428571f,  0.2607142857142857f, -0.0535714285714286f,
                             -0.0107142857142857f};
__constant__ float cG1[5] = {-0.05f, -0.25f, 0.6f, -0.25f, -0.05f};

__device__ float g_Z[8 * 512 * 512 * 3];

__device__ __forceinline__ int refl(int p, int L) {
  return p < 0 ? (-1 - p) : (p >= L ? (2 * L - 1 - p) : p);
}
__device__ __forceinline__ float comb(float x, float y, int rp, int wp) {
  return rp == 0 ? (x + y) : (wp == 0 ? (x - y) : (y - x));
}

// ---------------- kA: level-1 fused, tile = 8 Z-rows x 128 Z-cols (R11) -----
__global__ __launch_bounds__(256) void kA_lvl1(const float* __restrict__ low,
                                               const float* __restrict__ hi1) {
  __shared__ float sY1[8][228];
  __shared__ float sY2[8][228];
  int kw0 = blockIdx.x * 32;
  int kp  = blockIdx.y;
  int b   = blockIdx.z;
  int t   = threadIdx.x;

  if (t < 228) {
    int z = t / 3, c = t - 3 * z;
    int yc = 2 * kw0 - 6 + z;
    int yr = refl(yc, 256);
    int jj = yr >> 1, wp = yr & 1;
    const bool interior = (kp >= 2 && kp <= 61);
    const int base = 4 * kp - 6;

    const float* lowb = low + ((b * 256) * 256 + yr) * 3 + c;
    const float* hb   = hi1 + ((b * 128) * 128 + jj) * 36 + c;

    int pv[16];
#pragma unroll
    for (int v = 0; v < 16; v++) {
      int p = base + v;
      pv[v] = interior ? p : refl(p, 256);
    }

    float a[8], hl[8];
    {
      float xl[16], xB[16];
#pragma unroll
      for (int v = 0; v < 16; v++) {
        int p = pv[v];
        xl[v] = lowb[p * 768];
        int i = p >> 1, rp = p & 1;
        const float* q = hb + i * 4608 + ((rp ^ wp) ? 18 : 0);
        xB[v] = comb(q[6], q[9], rp, wp);
      }
#pragma unroll
      for (int dk = 0; dk < 2; dk++)
#pragma unroll
        for (int s = 0; s < 4; s++) {
          int v0 = 2 * dk + 12 + (s & 1);
          float aa = 0.f, hh = 0.f;
#pragma unroll
          for (int j = 0; j < 7; j++) {
            float f = cF0[s][j];
            aa += f * xl[v0 - 2 * j];
            hh += f * xB[v0 - 2 * j];
          }
          a[4 * dk + s] = aa; hl[4 * dk + s] = hh;
        }
    }
    {
      float xC[16], xD[16];
#pragma unroll
      for (int v = 0; v < 16; v++) {
        int p = pv[v];
        int i = p >> 1, rp = p & 1;
        const float* q = hb + i * 4608 + ((rp ^ wp) ? 18 : 0);
        xC[v] = comb(q[0], q[15], rp, wp);
        xD[v] = comb(q[3], q[12], rp, wp);
      }
#pragma unroll
      for (int dk = 0; dk < 2; dk++)
#pragma unroll
        for (int s = 0; s < 4; s++) {
          int v1 = 2 * dk + 13 - (s & 1);
          float lh = 0.f, hh = 0.f;
#pragma unroll
          for (int j = 0; j < 7; j++) {
            float f = cF1[s][j];
            lh += f * xC[v1 - 2 * j];
            hh += f * xD[v1 - 2 * j];
          }
          sY1[4 * dk + s][t] = a[4 * dk + s] + SCQ * lh;
          sY2[4 * dk + s][t] = SCQ * (hl[4 * dk + s] + hh);
        }
    }
  }
  __syncthreads();

  int row = t >> 5, cp = t & 31;
  float O[12];
#pragma unroll
  for (int i = 0; i < 12; i++) O[i] = 0.f;
#pragma unroll
  for (int s = 0; s < 4; s++) {
    int v0 = 2 * cp + 12 + (s & 1), v1 = 2 * cp + 13 - (s & 1);
#pragma unroll
    for (int j = 0; j < 7; j++) {
      float f0 = cF0[s][j], f1 = cF1[s][j];
#pragma unroll
      for (int c = 0; c < 3; c++) {
        O[s * 3 + c] += f0 * sY1[row][(v0 - 2 * j) * 3 + c]
                      + f1 * sY2[row][(v1 - 2 * j) * 3 + c];
      }
    }
  }
  int ob = ((b * 512 + 8 * kp + row) * 512 + 4 * (kw0 + cp)) * 3;
  float4* po = (float4*)(g_Z + ob);
#pragma unroll
  for (int m = 0; m < 3; m++)
    po[m] = make_float4(O[4 * m], O[4 * m + 1], O[4 * m + 2], O[4 * m + 3]);
}

// ---------------- kB: level-0 fused, hi0 row-staged in smem -----------------
// grid (8, 64, 8); block 256; dynamic smem 54912 B:
//   sS  [8*1296]  hi0 cell rows i0..i0+7, cells jbC..jbC+35 (contiguous spans)
//   sY1 [8][210], sY2 [8][210]
__global__ __launch_bounds__(256) void kB_lvl0(const float* __restrict__ hi0,
                                               float* __restrict__ out) {
  extern __shared__ float sm[];
  float* sS  = sm;                    // 10368
  float* sY1 = sm + 10368;            // 1680
  float* sY2 = sm + 12048;            // 1680
  int wt = blockIdx.x * 64;
  int rt = blockIdx.y * 8;
  int b  = blockIdx.z;
  int t  = threadIdx.x;
  int i0  = (rt >> 1) - 2;
  int jbC = (wt >> 1) - 2;
  jbC = jbC < 0 ? 0 : (jbC > 220 ? 220 : jbC);
  const float* hbase = hi0 + b * 2359296;

  // ---- stage: 8 contiguous 1296-float row spans, float4-coalesced ----
#pragma unroll
  for (int r = 0; r < 8; r++) {
    int ir = i0 + r;
    ir = ir < 0 ? 0 : (ir > 255 ? 255 : ir);
    const float4* src = (const float4*)(hbase + ir * 9216 + jbC * 36);
    float4* dst = (float4*)(sS + r * 1296);
    for (int e = t; e < 324; e += 256) dst[e] = src[e];
  }
  __syncthreads();

  if (t < 210) {
    int ucol = t / 3, c = t - 3 * ucol;
    int w  = wt - 3 + ucol;
    int wr = refl(w, 512);
    int jj = wr >> 1, wp = wr & 1;
    int scOff = (jj - jbC) * 36 + c;
    const float* zb = g_Z + ((b * 512) * 512 + wr) * 3 + c;
    const bool vint = (rt >= 4 && rt <= 500);

    float a1[8], a2[8];
    {
      float xz[14], xhl[14];
#pragma unroll
      for (int v = 0; v < 14; v++) {
        int p = rt - 3 + v;
        int pr = vint ? p : refl(p, 512);
        xz[v] = zb[pr * 1536];
        int r = (pr >> 1) - i0, rp = pr & 1;
        const float* qq = sS + r * 1296 + scOff + ((rp ^ wp) ? 18 : 0);
        xhl[v] = comb(qq[6], qq[9], rp, wp);
      }
#pragma unroll
      for (int s = 0; s < 8; s++) {
        float u1 = 0.f, u2 = 0.f;
#pragma unroll
        for (int j = 0; j < 7; j++) {
          float f = cG0[j];
          u1 += f * xz [s + 6 - j];
          u2 += f * xhl[s + 6 - j];
        }
        a1[s] = u1; a2[s] = u2;
      }
    }
    {
      float xlh[12], xhh[12];
#pragma unroll
      for (int v = 0; v < 12; v++) {
        int p = rt - 2 + v;
        int pr = vint ? p : refl(p, 512);
        int r = (pr >> 1) - i0, rp = pr & 1;
        const float* qq = sS + r * 1296 + scOff + ((rp ^ wp) ? 18 : 0);
        xlh[v] = comb(qq[0], qq[15], rp, wp);
        xhh[v] = comb(qq[3], qq[12], rp, wp);
      }
#pragma unroll
      for (int s = 0; s < 8; s++) {
        float lh = 0.f, hh = 0.f;
#pragma unroll
        for (int j = 0; j < 5; j++) {
          float f = cG1[j];
          lh += f * xlh[s + 4 - j];
          hh += f * xhh[s + 4 - j];
        }
        sY1[s * 210 + t] = a1[s] + SCQ * lh;
        sY2[s * 210 + t] = SCQ * (a2[s] + hh);
      }
    }
  }
  __syncthreads();

  int row = t >> 5, cp = t & 31;
  int cc0 = 2 * cp;
  float o[6];
#pragma unroll
  for (int d = 0; d < 2; d++) {
    int cc = cc0 + d;
#pragma unroll
    for (int ch = 0; ch < 3; ch++) {
      float acc = 0.f;
#pragma unroll
      for (int j = 0; j < 7; j++) acc += cG0[j] * sY1[row * 210 + (cc + 6 - j) * 3 + ch];
#pragma unroll
      for (int j = 0; j < 5; j++) acc += cG1[j] * sY2[row * 210 + (cc + 5 - j) * 3 + ch];
      o[d * 3 + ch] = acc;
    }
  }
  int ob = ((b * 512 + rt + row) * 512 + wt + cc0) * 3;
  float2* po = (float2*)(out + ob);
  po[0] = make_float2(o[0], o[1]);
  po[1] = make_float2(o[2], o[3]);
  po[2] = make_float2(o[4], o[5]);
}

extern "C" void kernel_launch(void* const* d_in, const int* in_sizes, int n_in,
                              void* d_out, int out_size) {
  const float *low = nullptr, *high0 = nullptr, *high1 = nullptr;
  for (int i = 0; i < n_in; i++) {
    if (in_sizes[i] == 8 * 256 * 256 * 3)       low   = (const float*)d_in[i];
    else if (in_sizes[i] == 8 * 256 * 256 * 36) high0 = (const float*)d_in[i];
    else if (in_sizes[i] == 8 * 128 * 128 * 36) high1 = (const float*)d_in[i];
  }
  float* out = (float*)d_out;

  static bool attr_done = false;
  if (!attr_done) {
    cudaFuncSetAttribute(kB_lvl0, cudaFuncAttributeMaxDynamicSharedMemorySize, 55296);
    attr_done = true;
  }

  kA_lvl1<<<dim3(4, 64, 8), 256>>>(low, high1);
  kB_lvl0<<<dim3(8, 64, 8), 256, 54912>>>(high0, out);
}